// round 9
// baseline (speedup 1.0000x reference)
#include <cuda_runtime.h>
#include <cuda_bf16.h>
#include <cstdint>
#include <cstdio>

// Problem constants
#define BATCH 2
#define NN    4096
#define ROWS  (BATCH*NN)      // 8192
#define IN_FT 512
#define OUT_FT 256
#define CAP   256
#define EPSN  1e-12f

// GEMM tile config
#define BM 128
#define BN 64
#define KC 32                 // K elements per smem chunk
#define LDS 40                // padded smem stride (bf16 elems): conflict-free ldmatrix

// ---------------- scratch (no allocations allowed) ----------------
__device__ int   g_cols[(size_t)ROWS*CAP];
__device__ float g_vals[(size_t)ROWS*CAP];
__device__ int   g_cnt[ROWS];
__device__ float g_seqfts[(size_t)ROWS*OUT_FT];
__device__ float g_out   [(size_t)ROWS*OUT_FT];
__device__ float g_q     [(size_t)ROWS*OUT_FT];
__device__ float g_k     [(size_t)ROWS*OUT_FT];
__device__ float g_rowd  [ROWS];
// bf16 split planes
__device__ __nv_bfloat16 g_seq_hi[(size_t)ROWS*IN_FT];
__device__ __nv_bfloat16 g_seq_lo[(size_t)ROWS*IN_FT];
__device__ __nv_bfloat16 g_out_hi[(size_t)ROWS*OUT_FT];
__device__ __nv_bfloat16 g_out_lo[(size_t)ROWS*OUT_FT];
__device__ __nv_bfloat16 g_ctx_hi[(size_t)ROWS*OUT_FT];
__device__ __nv_bfloat16 g_ctx_lo[(size_t)ROWS*OUT_FT];
__device__ __nv_bfloat16 g_h_hi  [(size_t)ROWS*OUT_FT];
__device__ __nv_bfloat16 g_h_lo  [(size_t)ROWS*OUT_FT];
// packed weight planes
#define WOFF_FC 0
#define WOFF_Q  131072
#define WOFF_K  196608
#define WOFF_V1 262144
#define WOFF_V2 327680
#define WTOT    393216
__device__ __nv_bfloat16 g_w_hi[WTOT];
__device__ __nv_bfloat16 g_w_lo[WTOT];

// ---------------- mma.sync helpers (arch-agnostic tensor path) ----------------
__device__ __forceinline__ void mma_bf16(float* c, const uint32_t* a, const uint32_t* b) {
    asm volatile("mma.sync.aligned.m16n8k16.row.col.f32.bf16.bf16.f32 "
        "{%0,%1,%2,%3}, {%4,%5,%6,%7}, {%8,%9}, {%0,%1,%2,%3};"
        : "+f"(c[0]), "+f"(c[1]), "+f"(c[2]), "+f"(c[3])
        : "r"(a[0]), "r"(a[1]), "r"(a[2]), "r"(a[3]), "r"(b[0]), "r"(b[1]));
}
__device__ __forceinline__ void ldsm_x4(uint32_t* r, uint32_t addr) {
    asm volatile("ldmatrix.sync.aligned.m8n8.x4.shared.b16 {%0,%1,%2,%3}, [%4];"
        : "=r"(r[0]), "=r"(r[1]), "=r"(r[2]), "=r"(r[3]) : "r"(addr));
}

// ---------------- block reductions (256 threads) ----------------
__device__ __forceinline__ float blk_sum256(float v, float* sh) {
    int t = threadIdx.x, lane = t & 31, w = t >> 5;
    #pragma unroll
    for (int o = 16; o; o >>= 1) v += __shfl_xor_sync(0xffffffffu, v, o);
    if (lane == 0) sh[w] = v;
    __syncthreads();
    if (w == 0) {
        float s = (lane < 8) ? sh[lane] : 0.f;
        #pragma unroll
        for (int o = 16; o; o >>= 1) s += __shfl_xor_sync(0xffffffffu, s, o);
        if (lane == 0) sh[0] = s;
    }
    __syncthreads();
    float r = sh[0];
    __syncthreads();
    return r;
}
__device__ __forceinline__ float blk_max256(float v, float* sh) {
    int t = threadIdx.x, lane = t & 31, w = t >> 5;
    #pragma unroll
    for (int o = 16; o; o >>= 1) v = fmaxf(v, __shfl_xor_sync(0xffffffffu, v, o));
    if (lane == 0) sh[w] = v;
    __syncthreads();
    if (w == 0) {
        float s = (lane < 8) ? sh[lane] : -3.0e38f;
        #pragma unroll
        for (int o = 16; o; o >>= 1) s = fmaxf(s, __shfl_xor_sync(0xffffffffu, s, o));
        if (lane == 0) sh[0] = s;
    }
    __syncthreads();
    float r = sh[0];
    __syncthreads();
    return r;
}

// ---------------- 1) sparse compaction: one warp per adj row ----------------
__global__ void build_sparse(const float* __restrict__ adj) {
    int gw = (blockIdx.x * blockDim.x + threadIdx.x) >> 5;
    int lane = threadIdx.x & 31;
    if (gw >= ROWS) return;
    const float* ar = adj + (size_t)gw * NN;
    int bbase = (gw >> 12) << 12;
    int base = 0;
    size_t o = (size_t)gw * CAP;
    #pragma unroll 1
    for (int it = 0; it < NN / 128; it++) {
        float4 v = ((const float4*)ar)[it * 32 + lane];
        float vv[4] = { v.x, v.y, v.z, v.w };
        #pragma unroll
        for (int j = 0; j < 4; j++) {
            bool nz = vv[j] > 0.f;
            unsigned m = __ballot_sync(0xffffffffu, nz);
            if (nz) {
                int pos = base + __popc(m & ((1u << lane) - 1u));
                if (pos < CAP) {
                    g_cols[o + pos] = bbase + it * 128 + lane * 4 + j;
                    g_vals[o + pos] = vv[j];
                }
            }
            base += __popc(m);
        }
    }
    if (lane == 0) g_cnt[gw] = min(base, CAP);
}

// ---------------- 2) fp32 -> bf16 hi/lo split converters ----------------
__global__ void conv_split(const float* __restrict__ x, __nv_bfloat16* __restrict__ hi,
                           __nv_bfloat16* __restrict__ lo, int n4) {
    int i = blockIdx.x * blockDim.x + threadIdx.x;
    if (i >= n4) return;
    float4 v = ((const float4*)x)[i];
    float f[4] = { v.x, v.y, v.z, v.w };
    ushort4 hh, ll;
    unsigned short* hp = &hh.x; unsigned short* lp = &ll.x;
    #pragma unroll
    for (int j = 0; j < 4; j++) {
        __nv_bfloat16 h = __float2bfloat16(f[j]);
        __nv_bfloat16 l = __float2bfloat16(f[j] - __bfloat162float(h));
        hp[j] = __bfloat16_as_ushort(h);
        lp[j] = __bfloat16_as_ushort(l);
    }
    ((ushort4*)hi)[i] = hh;
    ((ushort4*)lo)[i] = ll;
}

__global__ void conv_weights(const float* __restrict__ wfc, const float* __restrict__ wq,
                             const float* __restrict__ wk, const float* __restrict__ wv1,
                             const float* __restrict__ wv2) {
    int i = blockIdx.x * blockDim.x + threadIdx.x;
    if (i >= WTOT) return;
    float x;
    if      (i < WOFF_Q)  x = wfc[i];
    else if (i < WOFF_K)  x = wq [i - WOFF_Q];
    else if (i < WOFF_V1) x = wk [i - WOFF_K];
    else if (i < WOFF_V2) x = wv1[i - WOFF_V1];
    else                  x = wv2[i - WOFF_V2];
    __nv_bfloat16 h = __float2bfloat16(x);
    g_w_hi[i] = h;
    g_w_lo[i] = __float2bfloat16(x - __bfloat162float(h));
}

// ---------------- 3) split-bf16 mma.sync GEMM: C[m,n]=sum_k A[m,k]*W[n,k] ----------------
// A planes [M,K] bf16 row-major, W planes [N,K] bf16 row-major.
// CTA tile 128x64, 8 warps in 4(M)x2(N), warp tile 32x32.
// epi: 0 none, 1 prelu(alpha), 2 bias+prelu(alpha). outmode: 0 fp32 C, 1 bf16 planes.
__global__ __launch_bounds__(256, 2) void gemm_mma(
    const __nv_bfloat16* __restrict__ Ah, const __nv_bfloat16* __restrict__ Al,
    const __nv_bfloat16* __restrict__ Wh, const __nv_bfloat16* __restrict__ Wl,
    const float* __restrict__ bias, const float* __restrict__ alpha,
    float* __restrict__ C, __nv_bfloat16* __restrict__ Ch, __nv_bfloat16* __restrict__ Cl,
    int K, int epi, int outmode)
{
    __shared__ __align__(16) __nv_bfloat16 sAh[BM * LDS];
    __shared__ __align__(16) __nv_bfloat16 sAl[BM * LDS];
    __shared__ __align__(16) __nv_bfloat16 sBh[BN * LDS];
    __shared__ __align__(16) __nv_bfloat16 sBl[BN * LDS];

    const int t = threadIdx.x, lane = t & 31, wid = t >> 5;
    const int wm = wid & 3, wn = wid >> 2;
    const int m0 = blockIdx.y * BM, n0 = blockIdx.x * BN;

    float acc[2][4][4];
    #pragma unroll
    for (int i = 0; i < 2; i++)
        #pragma unroll
        for (int j = 0; j < 4; j++)
            #pragma unroll
            for (int l = 0; l < 4; l++) acc[i][j][l] = 0.f;

    // per-lane ldmatrix byte offsets (element offsets *2)
    uint32_t aAh_base = (uint32_t)__cvta_generic_to_shared(sAh);
    uint32_t aAl_base = (uint32_t)__cvta_generic_to_shared(sAl);
    uint32_t aBh_base = (uint32_t)__cvta_generic_to_shared(sBh);
    uint32_t aBl_base = (uint32_t)__cvta_generic_to_shared(sBl);
    uint32_t offA[2];
    #pragma unroll
    for (int mt = 0; mt < 2; mt++)
        offA[mt] = (uint32_t)(((wm * 32 + mt * 16 + (lane & 15)) * LDS + (lane >> 4) * 8) * 2);
    uint32_t offB[2];
    #pragma unroll
    for (int g = 0; g < 2; g++) {
        int nrow = wn * 32 + g * 16 + (lane & 7) + ((lane >> 4) & 1) * 8;
        int kof = ((lane >> 3) & 1) * 8;
        offB[g] = (uint32_t)((nrow * LDS + kof) * 2);
    }

    const int nchunk = K / KC;
    #pragma unroll 1
    for (int ko = 0; ko < nchunk; ko++) {
        const int k0 = ko * KC;
        #pragma unroll
        for (int i = 0; i < 2; i++) {
            int idx = t + i * 256;
            int row = idx >> 2, v = idx & 3;
            size_t go = (size_t)(m0 + row) * K + k0 + v * 8;
            *(uint4*)&sAh[row * LDS + v * 8] = *(const uint4*)&Ah[go];
            *(uint4*)&sAl[row * LDS + v * 8] = *(const uint4*)&Al[go];
        }
        {
            int row = t >> 2, v = t & 3;
            size_t go = (size_t)(n0 + row) * K + k0 + v * 8;
            *(uint4*)&sBh[row * LDS + v * 8] = *(const uint4*)&Wh[go];
            *(uint4*)&sBl[row * LDS + v * 8] = *(const uint4*)&Wl[go];
        }
        __syncthreads();

        #pragma unroll
        for (int ks = 0; ks < KC; ks += 16) {
            uint32_t ah[2][4], al[2][4], bh[2][4], bl[2][4];
            #pragma unroll
            for (int mt = 0; mt < 2; mt++) {
                ldsm_x4(ah[mt], aAh_base + offA[mt] + ks * 2);
                ldsm_x4(al[mt], aAl_base + offA[mt] + ks * 2);
            }
            #pragma unroll
            for (int g = 0; g < 2; g++) {
                ldsm_x4(bh[g], aBh_base + offB[g] + ks * 2);
                ldsm_x4(bl[g], aBl_base + offB[g] + ks * 2);
            }
            #pragma unroll
            for (int mt = 0; mt < 2; mt++)
                #pragma unroll
                for (int nb = 0; nb < 4; nb++) {
                    uint32_t bhj[2] = { bh[nb >> 1][(nb & 1) * 2], bh[nb >> 1][(nb & 1) * 2 + 1] };
                    uint32_t blj[2] = { bl[nb >> 1][(nb & 1) * 2], bl[nb >> 1][(nb & 1) * 2 + 1] };
                    mma_bf16(acc[mt][nb], ah[mt], bhj);
                    mma_bf16(acc[mt][nb], ah[mt], blj);
                    mma_bf16(acc[mt][nb], al[mt], bhj);
                }
        }
        __syncthreads();
    }

    // epilogue
    float av = (epi != 0) ? *alpha : 0.f;
    int mb = m0 + wm * 32 + (lane >> 2);
    int ncb = n0 + wn * 32 + (lane & 3) * 2;
    #pragma unroll
    for (int mt = 0; mt < 2; mt++)
        #pragma unroll
        for (int nb = 0; nb < 4; nb++)
            #pragma unroll
            for (int h = 0; h < 2; h++) {
                int m = mb + mt * 16 + h * 8;
                int n = ncb + nb * 8;
                float x0 = acc[mt][nb][h * 2 + 0];
                float x1 = acc[mt][nb][h * 2 + 1];
                if (epi == 2) { x0 += bias[n]; x1 += bias[n + 1]; }
                if (epi != 0) {
                    x0 = (x0 >= 0.f) ? x0 : av * x0;
                    x1 = (x1 >= 0.f) ? x1 : av * x1;
                }
                size_t co = (size_t)m * OUT_FT + n;
                if (outmode == 0) {
                    *(float2*)(C + co) = make_float2(x0, x1);
                } else {
                    __nv_bfloat16 h0 = __float2bfloat16(x0), h1 = __float2bfloat16(x1);
                    __nv_bfloat16 l0 = __float2bfloat16(x0 - __bfloat162float(h0));
                    __nv_bfloat16 l1 = __float2bfloat16(x1 - __bfloat162float(h1));
                    *(uint32_t*)(Ch + co) = (uint32_t)__bfloat16_as_ushort(h0) | ((uint32_t)__bfloat16_as_ushort(h1) << 16);
                    *(uint32_t*)(Cl + co) = (uint32_t)__bfloat16_as_ushort(l0) | ((uint32_t)__bfloat16_as_ushort(l1) << 16);
                }
            }
}

// ---------------- 4) SpMM + bf16 split epilogue ----------------
__global__ void spmm_kernel(const float* __restrict__ x, float* __restrict__ y,
                            __nv_bfloat16* __restrict__ yh, __nv_bfloat16* __restrict__ yl) {
    int row = blockIdx.x, t = threadIdx.x;
    __shared__ int   cs[CAP];
    __shared__ float vs[CAP];
    int nn = g_cnt[row];
    for (int j = t; j < nn; j += 256) {
        cs[j] = g_cols[(size_t)row * CAP + j];
        vs[j] = g_vals[(size_t)row * CAP + j];
    }
    __syncthreads();
    float acc = 0.f;
    #pragma unroll 4
    for (int j = 0; j < nn; j++)
        acc = fmaf(vs[j], x[(size_t)cs[j] * OUT_FT + t], acc);
    size_t idx = (size_t)row * OUT_FT + t;
    y[idx] = acc;
    __nv_bfloat16 h = __float2bfloat16(acc);
    yh[idx] = h;
    yl[idx] = __float2bfloat16(acc - __bfloat162float(h));
}

// ---------------- 5) normalize q,k in place; per-row ||q-k||^2 ----------------
__global__ void normalize_kernel(float* __restrict__ q, float* __restrict__ k,
                                 float* __restrict__ rowd) {
    __shared__ float red[8];
    int row = blockIdx.x, t = threadIdx.x;
    size_t idx = (size_t)row * OUT_FT + t;
    float qv = q[idx], kv = k[idx];
    float nq = sqrtf(blk_sum256(qv * qv, red));
    float nk = sqrtf(blk_sum256(kv * kv, red));
    float qn = qv / fmaxf(nq, EPSN);
    float kn = kv / fmaxf(nk, EPSN);
    q[idx] = qn; k[idx] = kn;
    float d = qn - kn;
    float ds = blk_sum256(d * d, red);
    if (t == 0) rowd[row] = ds;
}

__global__ void reduce_divloss(const float* __restrict__ rowd, float* __restrict__ dst) {
    __shared__ float sh[1024];
    int t = threadIdx.x;
    float s = 0.f;
    for (int i = t; i < ROWS; i += 1024) s += rowd[i];
    sh[t] = s; __syncthreads();
    #pragma unroll
    for (int o = 512; o; o >>= 1) { if (t < o) sh[t] += sh[t + o]; __syncthreads(); }
    if (t == 0) *dst = sh[0] / (float)ROWS;
}

// ---------------- 6) sparse masked softmax attention -> ctx (bf16 planes) ----------------
__global__ void attn_kernel(const float* __restrict__ q, const float* __restrict__ k,
                            const float* __restrict__ outm,
                            __nv_bfloat16* __restrict__ ch, __nv_bfloat16* __restrict__ cl) {
    int row = blockIdx.x, t = threadIdx.x, lane = t & 31, w = t >> 5;
    __shared__ float qs[OUT_FT];
    __shared__ int   cs[CAP];
    __shared__ float ss[CAP];
    __shared__ float red[8];
    int nn = g_cnt[row];
    qs[t] = q[(size_t)row * OUT_FT + t];
    for (int j = t; j < nn; j += 256) cs[j] = g_cols[(size_t)row * CAP + j];
    __syncthreads();
    for (int j = w; j < nn; j += 8) {
        const float* kr = k + (size_t)cs[j] * OUT_FT;
        float p = 0.f;
        #pragma unroll
        for (int i = 0; i < 8; i++) p = fmaf(qs[lane + 32 * i], kr[lane + 32 * i], p);
        #pragma unroll
        for (int o = 16; o; o >>= 1) p += __shfl_xor_sync(0xffffffffu, p, o);
        if (lane == 0) ss[j] = p;
    }
    __syncthreads();
    float mx = -3.0e38f;
    for (int j = t; j < nn; j += 256) mx = fmaxf(mx, ss[j]);
    mx = blk_max256(mx, red);
    float sm = 0.f;
    for (int j = t; j < nn; j += 256) { float e = expf(ss[j] - mx); ss[j] = e; sm += e; }
    sm = blk_sum256(sm, red);
    float inv = 1.f / sm;
    float acc = 0.f;
    #pragma unroll 4
    for (int j = 0; j < nn; j++)
        acc = fmaf(ss[j] * inv, outm[(size_t)cs[j] * OUT_FT + t], acc);
    size_t idx = (size_t)row * OUT_FT + t;
    __nv_bfloat16 h = __float2bfloat16(acc);
    ch[idx] = h;
    cl[idx] = __float2bfloat16(acc - __bfloat162float(h));
}

// ---------------- host ----------------
extern "C" void kernel_launch(void* const* d_in, const int* in_sizes, int n_in,
                              void* d_out, int out_size) {
    const float* seq   = (const float*)d_in[0];
    const float* adj   = (const float*)d_in[1];
    const float* W_fc  = (const float*)d_in[2];
    const float* W_q   = (const float*)d_in[3];
    const float* W_k   = (const float*)d_in[4];
    const float* W_v1  = (const float*)d_in[5];
    const float* W_v2  = (const float*)d_in[6];
    const float* a_v   = (const float*)d_in[7];
    const float* a_act = (const float*)d_in[8];
    const float* bias  = (const float*)d_in[9];
    float* out = (float*)d_out;

    float *p_seqfts, *p_out, *p_q, *p_k, *p_rowd;
    __nv_bfloat16 *p_seq_hi, *p_seq_lo, *p_out_hi, *p_out_lo, *p_ctx_hi, *p_ctx_lo, *p_h_hi, *p_h_lo, *p_w_hi, *p_w_lo;
    cudaGetSymbolAddress((void**)&p_seqfts, g_seqfts);
    cudaGetSymbolAddress((void**)&p_out,    g_out);
    cudaGetSymbolAddress((void**)&p_q,      g_q);
    cudaGetSymbolAddress((void**)&p_k,      g_k);
    cudaGetSymbolAddress((void**)&p_rowd,   g_rowd);
    cudaGetSymbolAddress((void**)&p_seq_hi, g_seq_hi);
    cudaGetSymbolAddress((void**)&p_seq_lo, g_seq_lo);
    cudaGetSymbolAddress((void**)&p_out_hi, g_out_hi);
    cudaGetSymbolAddress((void**)&p_out_lo, g_out_lo);
    cudaGetSymbolAddress((void**)&p_ctx_hi, g_ctx_hi);
    cudaGetSymbolAddress((void**)&p_ctx_lo, g_ctx_lo);
    cudaGetSymbolAddress((void**)&p_h_hi,   g_h_hi);
    cudaGetSymbolAddress((void**)&p_h_lo,   g_h_lo);
    cudaGetSymbolAddress((void**)&p_w_hi,   g_w_hi);
    cudaGetSymbolAddress((void**)&p_w_lo,   g_w_lo);

    dim3 gg(OUT_FT / BN, ROWS / BM);   // (4, 64)

    build_sparse<<<ROWS / 8, 256>>>(adj);
    conv_split<<<(ROWS * IN_FT / 4 + 255) / 256, 256>>>(seq, p_seq_hi, p_seq_lo, ROWS * IN_FT / 4);
    conv_weights<<<(WTOT + 255) / 256, 256>>>(W_fc, W_q, W_k, W_v1, W_v2);

    gemm_mma<<<gg, 256>>>(p_seq_hi, p_seq_lo, p_w_hi + WOFF_FC, p_w_lo + WOFF_FC,
                          nullptr, nullptr, p_seqfts, nullptr, nullptr, IN_FT, 0, 0);
    spmm_kernel<<<ROWS, 256>>>(p_seqfts, p_out, p_out_hi, p_out_lo);
    gemm_mma<<<gg, 256>>>(p_out_hi, p_out_lo, p_w_hi + WOFF_Q, p_w_lo + WOFF_Q,
                          nullptr, nullptr, p_q, nullptr, nullptr, OUT_FT, 0, 0);
    gemm_mma<<<gg, 256>>>(p_out_hi, p_out_lo, p_w_hi + WOFF_K, p_w_lo + WOFF_K,
                          nullptr, nullptr, p_k, nullptr, nullptr, OUT_FT, 0, 0);
    normalize_kernel<<<ROWS, 256>>>(p_q, p_k, p_rowd);
    if (out_size >= ROWS * OUT_FT + 1)
        reduce_divloss<<<1, 1024>>>(p_rowd, out + (size_t)ROWS * OUT_FT);
    attn_kernel<<<ROWS, 256>>>(p_q, p_k, p_out, p_ctx_hi, p_ctx_lo);
    gemm_mma<<<gg, 256>>>(p_ctx_hi, p_ctx_lo, p_w_hi + WOFF_V1, p_w_lo + WOFF_V1,
                          nullptr, a_v, nullptr, p_h_hi, p_h_lo, OUT_FT, 1, 1);
    gemm_mma<<<gg, 256>>>(p_h_hi, p_h_lo, p_w_hi + WOFF_V2, p_w_lo + WOFF_V2,
                          bias, a_act, out, nullptr, nullptr, OUT_FT, 2, 0);
}

// round 10
// speedup vs baseline: 1.0008x; 1.0008x over previous
#include <cuda_runtime.h>
#include <cuda_bf16.h>
#include <cstdint>
#include <cstdio>

// Problem constants
#define BATCH 2
#define NN    4096
#define ROWS  (BATCH*NN)      // 8192
#define IN_FT 512
#define OUT_FT 256
#define CAP   256
#define EPSN  1e-12f

// GEMM tile config
#define BM 128
#define BN 64
#define KC 32                 // K elements per smem chunk
#define LDS 40                // padded smem stride (bf16 elems): conflict-free ldmatrix

// ---------------- scratch (no allocations allowed) ----------------
__device__ int   g_cols[(size_t)ROWS*CAP];
__device__ float g_vals[(size_t)ROWS*CAP];
__device__ int   g_cnt[ROWS];
__device__ float g_seqfts[(size_t)ROWS*OUT_FT];
__device__ float g_out   [(size_t)ROWS*OUT_FT];
__device__ float g_q     [(size_t)ROWS*OUT_FT];
__device__ float g_k     [(size_t)ROWS*OUT_FT];
__device__ float g_rowd  [ROWS];
// bf16 split planes
__device__ __nv_bfloat16 g_seq_hi[(size_t)ROWS*IN_FT];
__device__ __nv_bfloat16 g_seq_lo[(size_t)ROWS*IN_FT];
__device__ __nv_bfloat16 g_out_hi[(size_t)ROWS*OUT_FT];
__device__ __nv_bfloat16 g_out_lo[(size_t)ROWS*OUT_FT];
__device__ __nv_bfloat16 g_ctx_hi[(size_t)ROWS*OUT_FT];
__device__ __nv_bfloat16 g_ctx_lo[(size_t)ROWS*OUT_FT];
__device__ __nv_bfloat16 g_h_hi  [(size_t)ROWS*OUT_FT];
__device__ __nv_bfloat16 g_h_lo  [(size_t)ROWS*OUT_FT];
// packed weight planes
#define WOFF_FC 0
#define WOFF_Q  131072
#define WOFF_K  196608
#define WOFF_V1 262144
#define WOFF_V2 327680
#define WTOT    393216
__device__ __nv_bfloat16 g_w_hi[WTOT];
__device__ __nv_bfloat16 g_w_lo[WTOT];

// ---------------- mma.sync helpers (arch-agnostic tensor path) ----------------
__device__ __forceinline__ void mma_bf16(float* c, const uint32_t* a, const uint32_t* b) {
    asm volatile("mma.sync.aligned.m16n8k16.row.col.f32.bf16.bf16.f32 "
        "{%0,%1,%2,%3}, {%4,%5,%6,%7}, {%8,%9}, {%0,%1,%2,%3};"
        : "+f"(c[0]), "+f"(c[1]), "+f"(c[2]), "+f"(c[3])
        : "r"(a[0]), "r"(a[1]), "r"(a[2]), "r"(a[3]), "r"(b[0]), "r"(b[1]));
}
__device__ __forceinline__ void ldsm_x4(uint32_t* r, uint32_t addr) {
    asm volatile("ldmatrix.sync.aligned.m8n8.x4.shared.b16 {%0,%1,%2,%3}, [%4];"
        : "=r"(r[0]), "=r"(r[1]), "=r"(r[2]), "=r"(r[3]) : "r"(addr));
}

// ---------------- block reductions (256 threads) ----------------
__device__ __forceinline__ float blk_sum256(float v, float* sh) {
    int t = threadIdx.x, lane = t & 31, w = t >> 5;
    #pragma unroll
    for (int o = 16; o; o >>= 1) v += __shfl_xor_sync(0xffffffffu, v, o);
    if (lane == 0) sh[w] = v;
    __syncthreads();
    if (w == 0) {
        float s = (lane < 8) ? sh[lane] : 0.f;
        #pragma unroll
        for (int o = 16; o; o >>= 1) s += __shfl_xor_sync(0xffffffffu, s, o);
        if (lane == 0) sh[0] = s;
    }
    __syncthreads();
    float r = sh[0];
    __syncthreads();
    return r;
}
__device__ __forceinline__ float blk_max256(float v, float* sh) {
    int t = threadIdx.x, lane = t & 31, w = t >> 5;
    #pragma unroll
    for (int o = 16; o; o >>= 1) v = fmaxf(v, __shfl_xor_sync(0xffffffffu, v, o));
    if (lane == 0) sh[w] = v;
    __syncthreads();
    if (w == 0) {
        float s = (lane < 8) ? sh[lane] : -3.0e38f;
        #pragma unroll
        for (int o = 16; o; o >>= 1) s = fmaxf(s, __shfl_xor_sync(0xffffffffu, s, o));
        if (lane == 0) sh[0] = s;
    }
    __syncthreads();
    float r = sh[0];
    __syncthreads();
    return r;
}

// ---------------- 1) sparse compaction: one warp per adj row ----------------
__global__ void build_sparse(const float* __restrict__ adj) {
    int gw = (blockIdx.x * blockDim.x + threadIdx.x) >> 5;
    int lane = threadIdx.x & 31;
    if (gw >= ROWS) return;
    const float* ar = adj + (size_t)gw * NN;
    int bbase = (gw >> 12) << 12;
    int base = 0;
    size_t o = (size_t)gw * CAP;
    #pragma unroll 1
    for (int it = 0; it < NN / 128; it++) {
        float4 v = ((const float4*)ar)[it * 32 + lane];
        float vv[4] = { v.x, v.y, v.z, v.w };
        #pragma unroll
        for (int j = 0; j < 4; j++) {
            bool nz = vv[j] > 0.f;
            unsigned m = __ballot_sync(0xffffffffu, nz);
            if (nz) {
                int pos = base + __popc(m & ((1u << lane) - 1u));
                if (pos < CAP) {
                    g_cols[o + pos] = bbase + it * 128 + lane * 4 + j;
                    g_vals[o + pos] = vv[j];
                }
            }
            base += __popc(m);
        }
    }
    if (lane == 0) g_cnt[gw] = min(base, CAP);
}

// ---------------- 2) fp32 -> bf16 hi/lo split converters ----------------
__global__ void conv_split(const float* __restrict__ x, __nv_bfloat16* __restrict__ hi,
                           __nv_bfloat16* __restrict__ lo, int n4) {
    int i = blockIdx.x * blockDim.x + threadIdx.x;
    if (i >= n4) return;
    float4 v = ((const float4*)x)[i];
    float f[4] = { v.x, v.y, v.z, v.w };
    ushort4 hh, ll;
    unsigned short* hp = &hh.x; unsigned short* lp = &ll.x;
    #pragma unroll
    for (int j = 0; j < 4; j++) {
        __nv_bfloat16 h = __float2bfloat16(f[j]);
        __nv_bfloat16 l = __float2bfloat16(f[j] - __bfloat162float(h));
        hp[j] = __bfloat16_as_ushort(h);
        lp[j] = __bfloat16_as_ushort(l);
    }
    ((ushort4*)hi)[i] = hh;
    ((ushort4*)lo)[i] = ll;
}

__global__ void conv_weights(const float* __restrict__ wfc, const float* __restrict__ wq,
                             const float* __restrict__ wk, const float* __restrict__ wv1,
                             const float* __restrict__ wv2) {
    int i = blockIdx.x * blockDim.x + threadIdx.x;
    if (i >= WTOT) return;
    float x;
    if      (i < WOFF_Q)  x = wfc[i];
    else if (i < WOFF_K)  x = wq [i - WOFF_Q];
    else if (i < WOFF_V1) x = wk [i - WOFF_K];
    else if (i < WOFF_V2) x = wv1[i - WOFF_V1];
    else                  x = wv2[i - WOFF_V2];
    __nv_bfloat16 h = __float2bfloat16(x);
    g_w_hi[i] = h;
    g_w_lo[i] = __float2bfloat16(x - __bfloat162float(h));
}

// ---------------- 3) split-bf16 mma.sync GEMM: C[m,n]=sum_k A[m,k]*W[n,k] ----------------
// A planes [M,K] bf16 row-major, W planes [N,K] bf16 row-major.
// CTA tile 128x64, 8 warps in 4(M)x2(N), warp tile 32x32.
// epi: 0 none, 1 prelu(alpha), 2 bias+prelu(alpha). outmode: 0 fp32 C, 1 bf16 planes.
__global__ __launch_bounds__(256, 2) void gemm_mma(
    const __nv_bfloat16* __restrict__ Ah, const __nv_bfloat16* __restrict__ Al,
    const __nv_bfloat16* __restrict__ Wh, const __nv_bfloat16* __restrict__ Wl,
    const float* __restrict__ bias, const float* __restrict__ alpha,
    float* __restrict__ C, __nv_bfloat16* __restrict__ Ch, __nv_bfloat16* __restrict__ Cl,
    int K, int epi, int outmode)
{
    __shared__ __align__(16) __nv_bfloat16 sAh[BM * LDS];
    __shared__ __align__(16) __nv_bfloat16 sAl[BM * LDS];
    __shared__ __align__(16) __nv_bfloat16 sBh[BN * LDS];
    __shared__ __align__(16) __nv_bfloat16 sBl[BN * LDS];

    const int t = threadIdx.x, lane = t & 31, wid = t >> 5;
    const int wm = wid & 3, wn = wid >> 2;
    const int m0 = blockIdx.y * BM, n0 = blockIdx.x * BN;

    float acc[2][4][4];
    #pragma unroll
    for (int i = 0; i < 2; i++)
        #pragma unroll
        for (int j = 0; j < 4; j++)
            #pragma unroll
            for (int l = 0; l < 4; l++) acc[i][j][l] = 0.f;

    // per-lane ldmatrix byte offsets (element offsets *2)
    uint32_t aAh_base = (uint32_t)__cvta_generic_to_shared(sAh);
    uint32_t aAl_base = (uint32_t)__cvta_generic_to_shared(sAl);
    uint32_t aBh_base = (uint32_t)__cvta_generic_to_shared(sBh);
    uint32_t aBl_base = (uint32_t)__cvta_generic_to_shared(sBl);
    uint32_t offA[2];
    #pragma unroll
    for (int mt = 0; mt < 2; mt++)
        offA[mt] = (uint32_t)(((wm * 32 + mt * 16 + (lane & 15)) * LDS + (lane >> 4) * 8) * 2);
    uint32_t offB[2];
    #pragma unroll
    for (int g = 0; g < 2; g++) {
        int nrow = wn * 32 + g * 16 + (lane & 7) + ((lane >> 4) & 1) * 8;
        int kof = ((lane >> 3) & 1) * 8;
        offB[g] = (uint32_t)((nrow * LDS + kof) * 2);
    }

    const int nchunk = K / KC;
    #pragma unroll 1
    for (int ko = 0; ko < nchunk; ko++) {
        const int k0 = ko * KC;
        #pragma unroll
        for (int i = 0; i < 2; i++) {
            int idx = t + i * 256;
            int row = idx >> 2, v = idx & 3;
            size_t go = (size_t)(m0 + row) * K + k0 + v * 8;
            *(uint4*)&sAh[row * LDS + v * 8] = *(const uint4*)&Ah[go];
            *(uint4*)&sAl[row * LDS + v * 8] = *(const uint4*)&Al[go];
        }
        {
            int row = t >> 2, v = t & 3;
            size_t go = (size_t)(n0 + row) * K + k0 + v * 8;
            *(uint4*)&sBh[row * LDS + v * 8] = *(const uint4*)&Wh[go];
            *(uint4*)&sBl[row * LDS + v * 8] = *(const uint4*)&Wl[go];
        }
        __syncthreads();

        #pragma unroll
        for (int ks = 0; ks < KC; ks += 16) {
            uint32_t ah[2][4], al[2][4], bh[2][4], bl[2][4];
            #pragma unroll
            for (int mt = 0; mt < 2; mt++) {
                ldsm_x4(ah[mt], aAh_base + offA[mt] + ks * 2);
                ldsm_x4(al[mt], aAl_base + offA[mt] + ks * 2);
            }
            #pragma unroll
            for (int g = 0; g < 2; g++) {
                ldsm_x4(bh[g], aBh_base + offB[g] + ks * 2);
                ldsm_x4(bl[g], aBl_base + offB[g] + ks * 2);
            }
            #pragma unroll
            for (int mt = 0; mt < 2; mt++)
                #pragma unroll
                for (int nb = 0; nb < 4; nb++) {
                    uint32_t bhj[2] = { bh[nb >> 1][(nb & 1) * 2], bh[nb >> 1][(nb & 1) * 2 + 1] };
                    uint32_t blj[2] = { bl[nb >> 1][(nb & 1) * 2], bl[nb >> 1][(nb & 1) * 2 + 1] };
                    mma_bf16(acc[mt][nb], ah[mt], bhj);
                    mma_bf16(acc[mt][nb], ah[mt], blj);
                    mma_bf16(acc[mt][nb], al[mt], bhj);
                }
        }
        __syncthreads();
    }

    // epilogue
    float av = (epi != 0) ? *alpha : 0.f;
    int mb = m0 + wm * 32 + (lane >> 2);
    int ncb = n0 + wn * 32 + (lane & 3) * 2;
    #pragma unroll
    for (int mt = 0; mt < 2; mt++)
        #pragma unroll
        for (int nb = 0; nb < 4; nb++)
            #pragma unroll
            for (int h = 0; h < 2; h++) {
                int m = mb + mt * 16 + h * 8;
                int n = ncb + nb * 8;
                float x0 = acc[mt][nb][h * 2 + 0];
                float x1 = acc[mt][nb][h * 2 + 1];
                if (epi == 2) { x0 += bias[n]; x1 += bias[n + 1]; }
                if (epi != 0) {
                    x0 = (x0 >= 0.f) ? x0 : av * x0;
                    x1 = (x1 >= 0.f) ? x1 : av * x1;
                }
                size_t co = (size_t)m * OUT_FT + n;
                if (outmode == 0) {
                    *(float2*)(C + co) = make_float2(x0, x1);
                } else {
                    __nv_bfloat16 h0 = __float2bfloat16(x0), h1 = __float2bfloat16(x1);
                    __nv_bfloat16 l0 = __float2bfloat16(x0 - __bfloat162float(h0));
                    __nv_bfloat16 l1 = __float2bfloat16(x1 - __bfloat162float(h1));
                    *(uint32_t*)(Ch + co) = (uint32_t)__bfloat16_as_ushort(h0) | ((uint32_t)__bfloat16_as_ushort(h1) << 16);
                    *(uint32_t*)(Cl + co) = (uint32_t)__bfloat16_as_ushort(l0) | ((uint32_t)__bfloat16_as_ushort(l1) << 16);
                }
            }
}

// ---------------- 4) SpMM + bf16 split epilogue ----------------
__global__ void spmm_kernel(const float* __restrict__ x, float* __restrict__ y,
                            __nv_bfloat16* __restrict__ yh, __nv_bfloat16* __restrict__ yl) {
    int row = blockIdx.x, t = threadIdx.x;
    __shared__ int   cs[CAP];
    __shared__ float vs[CAP];
    int nn = g_cnt[row];
    for (int j = t; j < nn; j += 256) {
        cs[j] = g_cols[(size_t)row * CAP + j];
        vs[j] = g_vals[(size_t)row * CAP + j];
    }
    __syncthreads();
    float acc = 0.f;
    #pragma unroll 4
    for (int j = 0; j < nn; j++)
        acc = fmaf(vs[j], x[(size_t)cs[j] * OUT_FT + t], acc);
    size_t idx = (size_t)row * OUT_FT + t;
    y[idx] = acc;
    __nv_bfloat16 h = __float2bfloat16(acc);
    yh[idx] = h;
    yl[idx] = __float2bfloat16(acc - __bfloat162float(h));
}

// ---------------- 5) normalize q,k in place; per-row ||q-k||^2 ----------------
__global__ void normalize_kernel(float* __restrict__ q, float* __restrict__ k,
                                 float* __restrict__ rowd) {
    __shared__ float red[8];
    int row = blockIdx.x, t = threadIdx.x;
    size_t idx = (size_t)row * OUT_FT + t;
    float qv = q[idx], kv = k[idx];
    float nq = sqrtf(blk_sum256(qv * qv, red));
    float nk = sqrtf(blk_sum256(kv * kv, red));
    float qn = qv / fmaxf(nq, EPSN);
    float kn = kv / fmaxf(nk, EPSN);
    q[idx] = qn; k[idx] = kn;
    float d = qn - kn;
    float ds = blk_sum256(d * d, red);
    if (t == 0) rowd[row] = ds;
}

__global__ void reduce_divloss(const float* __restrict__ rowd, float* __restrict__ dst) {
    __shared__ float sh[1024];
    int t = threadIdx.x;
    float s = 0.f;
    for (int i = t; i < ROWS; i += 1024) s += rowd[i];
    sh[t] = s; __syncthreads();
    #pragma unroll
    for (int o = 512; o; o >>= 1) { if (t < o) sh[t] += sh[t + o]; __syncthreads(); }
    if (t == 0) *dst = sh[0] / (float)ROWS;
}

// ---------------- 6) sparse masked softmax attention -> ctx (bf16 planes) ----------------
__global__ void attn_kernel(const float* __restrict__ q, const float* __restrict__ k,
                            const float* __restrict__ outm,
                            __nv_bfloat16* __restrict__ ch, __nv_bfloat16* __restrict__ cl) {
    int row = blockIdx.x, t = threadIdx.x, lane = t & 31, w = t >> 5;
    __shared__ float qs[OUT_FT];
    __shared__ int   cs[CAP];
    __shared__ float ss[CAP];
    __shared__ float red[8];
    int nn = g_cnt[row];
    qs[t] = q[(size_t)row * OUT_FT + t];
    for (int j = t; j < nn; j += 256) cs[j] = g_cols[(size_t)row * CAP + j];
    __syncthreads();
    for (int j = w; j < nn; j += 8) {
        const float* kr = k + (size_t)cs[j] * OUT_FT;
        float p = 0.f;
        #pragma unroll
        for (int i = 0; i < 8; i++) p = fmaf(qs[lane + 32 * i], kr[lane + 32 * i], p);
        #pragma unroll
        for (int o = 16; o; o >>= 1) p += __shfl_xor_sync(0xffffffffu, p, o);
        if (lane == 0) ss[j] = p;
    }
    __syncthreads();
    float mx = -3.0e38f;
    for (int j = t; j < nn; j += 256) mx = fmaxf(mx, ss[j]);
    mx = blk_max256(mx, red);
    float sm = 0.f;
    for (int j = t; j < nn; j += 256) { float e = expf(ss[j] - mx); ss[j] = e; sm += e; }
    sm = blk_sum256(sm, red);
    float inv = 1.f / sm;
    float acc = 0.f;
    #pragma unroll 4
    for (int j = 0; j < nn; j++)
        acc = fmaf(ss[j] * inv, outm[(size_t)cs[j] * OUT_FT + t], acc);
    size_t idx = (size_t)row * OUT_FT + t;
    __nv_bfloat16 h = __float2bfloat16(acc);
    ch[idx] = h;
    cl[idx] = __float2bfloat16(acc - __bfloat162float(h));
}

// ---------------- host ----------------
extern "C" void kernel_launch(void* const* d_in, const int* in_sizes, int n_in,
                              void* d_out, int out_size) {
    const float* seq   = (const float*)d_in[0];
    const float* adj   = (const float*)d_in[1];
    const float* W_fc  = (const float*)d_in[2];
    const float* W_q   = (const float*)d_in[3];
    const float* W_k   = (const float*)d_in[4];
    const float* W_v1  = (const float*)d_in[5];
    const float* W_v2  = (const float*)d_in[6];
    const float* a_v   = (const float*)d_in[7];
    const float* a_act = (const float*)d_in[8];
    const float* bias  = (const float*)d_in[9];
    float* out = (float*)d_out;

    float *p_seqfts, *p_out, *p_q, *p_k, *p_rowd;
    __nv_bfloat16 *p_seq_hi, *p_seq_lo, *p_out_hi, *p_out_lo, *p_ctx_hi, *p_ctx_lo, *p_h_hi, *p_h_lo, *p_w_hi, *p_w_lo;
    cudaGetSymbolAddress((void**)&p_seqfts, g_seqfts);
    cudaGetSymbolAddress((void**)&p_out,    g_out);
    cudaGetSymbolAddress((void**)&p_q,      g_q);
    cudaGetSymbolAddress((void**)&p_k,      g_k);
    cudaGetSymbolAddress((void**)&p_rowd,   g_rowd);
    cudaGetSymbolAddress((void**)&p_seq_hi, g_seq_hi);
    cudaGetSymbolAddress((void**)&p_seq_lo, g_seq_lo);
    cudaGetSymbolAddress((void**)&p_out_hi, g_out_hi);
    cudaGetSymbolAddress((void**)&p_out_lo, g_out_lo);
    cudaGetSymbolAddress((void**)&p_ctx_hi, g_ctx_hi);
    cudaGetSymbolAddress((void**)&p_ctx_lo, g_ctx_lo);
    cudaGetSymbolAddress((void**)&p_h_hi,   g_h_hi);
    cudaGetSymbolAddress((void**)&p_h_lo,   g_h_lo);
    cudaGetSymbolAddress((void**)&p_w_hi,   g_w_hi);
    cudaGetSymbolAddress((void**)&p_w_lo,   g_w_lo);

    dim3 gg(OUT_FT / BN, ROWS / BM);   // (4, 64)

    build_sparse<<<ROWS / 8, 256>>>(adj);
    conv_split<<<(ROWS * IN_FT / 4 + 255) / 256, 256>>>(seq, p_seq_hi, p_seq_lo, ROWS * IN_FT / 4);
    conv_weights<<<(WTOT + 255) / 256, 256>>>(W_fc, W_q, W_k, W_v1, W_v2);

    gemm_mma<<<gg, 256>>>(p_seq_hi, p_seq_lo, p_w_hi + WOFF_FC, p_w_lo + WOFF_FC,
                          nullptr, nullptr, p_seqfts, nullptr, nullptr, IN_FT, 0, 0);
    spmm_kernel<<<ROWS, 256>>>(p_seqfts, p_out, p_out_hi, p_out_lo);
    gemm_mma<<<gg, 256>>>(p_out_hi, p_out_lo, p_w_hi + WOFF_Q, p_w_lo + WOFF_Q,
                          nullptr, nullptr, p_q, nullptr, nullptr, OUT_FT, 0, 0);
    gemm_mma<<<gg, 256>>>(p_out_hi, p_out_lo, p_w_hi + WOFF_K, p_w_lo + WOFF_K,
                          nullptr, nullptr, p_k, nullptr, nullptr, OUT_FT, 0, 0);
    normalize_kernel<<<ROWS, 256>>>(p_q, p_k, p_rowd);
    if (out_size >= ROWS * OUT_FT + 1)
        reduce_divloss<<<1, 1024>>>(p_rowd, out + (size_t)ROWS * OUT_FT);
    attn_kernel<<<ROWS, 256>>>(p_q, p_k, p_out, p_ctx_hi, p_ctx_lo);
    gemm_mma<<<gg, 256>>>(p_ctx_hi, p_ctx_lo, p_w_hi + WOFF_V1, p_w_lo + WOFF_V1,
                          nullptr, a_v, nullptr, p_h_hi, p_h_lo, OUT_FT, 1, 1);
    gemm_mma<<<gg, 256>>>(p_h_hi, p_h_lo, p_w_hi + WOFF_V2, p_w_lo + WOFF_V2,
                          bias, a_act, out, nullptr, nullptr, OUT_FT, 2, 0);
}

// round 11
// speedup vs baseline: 1.0063x; 1.0056x over previous
#include <cuda_runtime.h>
#include <cuda_bf16.h>
#include <cstdint>
#include <cstdio>

// Problem constants
#define BATCH 2
#define NN    4096
#define ROWS  (BATCH*NN)      // 8192
#define IN_FT 512
#define OUT_FT 256
#define CAP   256
#define EPSN  1e-12f

// GEMM tile config
#define BM 128
#define BN 64
#define KC 32                 // K elements per smem chunk
#define LDS 40                // padded smem stride (bf16 elems): conflict-free ldmatrix

// ---------------- scratch (no allocations allowed) ----------------
__device__ int   g_cols[(size_t)ROWS*CAP];
__device__ float g_vals[(size_t)ROWS*CAP];
__device__ int   g_cnt[ROWS];
__device__ float g_seqfts[(size_t)ROWS*OUT_FT];
__device__ float g_out   [(size_t)ROWS*OUT_FT];
__device__ float g_q     [(size_t)ROWS*OUT_FT];
__device__ float g_k     [(size_t)ROWS*OUT_FT];
__device__ float g_rowd  [ROWS];
// bf16 split planes
__device__ __nv_bfloat16 g_seq_hi[(size_t)ROWS*IN_FT];
__device__ __nv_bfloat16 g_seq_lo[(size_t)ROWS*IN_FT];
__device__ __nv_bfloat16 g_out_hi[(size_t)ROWS*OUT_FT];
__device__ __nv_bfloat16 g_out_lo[(size_t)ROWS*OUT_FT];
__device__ __nv_bfloat16 g_ctx_hi[(size_t)ROWS*OUT_FT];
__device__ __nv_bfloat16 g_ctx_lo[(size_t)ROWS*OUT_FT];
__device__ __nv_bfloat16 g_h_hi  [(size_t)ROWS*OUT_FT];
__device__ __nv_bfloat16 g_h_lo  [(size_t)ROWS*OUT_FT];
// packed weight planes
#define WOFF_FC 0
#define WOFF_Q  131072
#define WOFF_K  196608
#define WOFF_V1 262144
#define WOFF_V2 327680
#define WTOT    393216
__device__ __nv_bfloat16 g_w_hi[WTOT];
__device__ __nv_bfloat16 g_w_lo[WTOT];

// ---------------- mma.sync helpers (arch-agnostic tensor path) ----------------
__device__ __forceinline__ void mma_bf16(float* c, const uint32_t* a, const uint32_t* b) {
    asm volatile("mma.sync.aligned.m16n8k16.row.col.f32.bf16.bf16.f32 "
        "{%0,%1,%2,%3}, {%4,%5,%6,%7}, {%8,%9}, {%0,%1,%2,%3};"
        : "+f"(c[0]), "+f"(c[1]), "+f"(c[2]), "+f"(c[3])
        : "r"(a[0]), "r"(a[1]), "r"(a[2]), "r"(a[3]), "r"(b[0]), "r"(b[1]));
}
__device__ __forceinline__ void ldsm_x4(uint32_t* r, uint32_t addr) {
    asm volatile("ldmatrix.sync.aligned.m8n8.x4.shared.b16 {%0,%1,%2,%3}, [%4];"
        : "=r"(r[0]), "=r"(r[1]), "=r"(r[2]), "=r"(r[3]) : "r"(addr));
}

// ---------------- block reductions (256 threads) ----------------
__device__ __forceinline__ float blk_sum256(float v, float* sh) {
    int t = threadIdx.x, lane = t & 31, w = t >> 5;
    #pragma unroll
    for (int o = 16; o; o >>= 1) v += __shfl_xor_sync(0xffffffffu, v, o);
    if (lane == 0) sh[w] = v;
    __syncthreads();
    if (w == 0) {
        float s = (lane < 8) ? sh[lane] : 0.f;
        #pragma unroll
        for (int o = 16; o; o >>= 1) s += __shfl_xor_sync(0xffffffffu, s, o);
        if (lane == 0) sh[0] = s;
    }
    __syncthreads();
    float r = sh[0];
    __syncthreads();
    return r;
}
__device__ __forceinline__ float blk_max256(float v, float* sh) {
    int t = threadIdx.x, lane = t & 31, w = t >> 5;
    #pragma unroll
    for (int o = 16; o; o >>= 1) v = fmaxf(v, __shfl_xor_sync(0xffffffffu, v, o));
    if (lane == 0) sh[w] = v;
    __syncthreads();
    if (w == 0) {
        float s = (lane < 8) ? sh[lane] : -3.0e38f;
        #pragma unroll
        for (int o = 16; o; o >>= 1) s = fmaxf(s, __shfl_xor_sync(0xffffffffu, s, o));
        if (lane == 0) sh[0] = s;
    }
    __syncthreads();
    float r = sh[0];
    __syncthreads();
    return r;
}

// ---------------- 1) sparse compaction: one warp per adj row ----------------
__global__ void build_sparse(const float* __restrict__ adj) {
    int gw = (blockIdx.x * blockDim.x + threadIdx.x) >> 5;
    int lane = threadIdx.x & 31;
    if (gw >= ROWS) return;
    const float* ar = adj + (size_t)gw * NN;
    int bbase = (gw >> 12) << 12;
    int base = 0;
    size_t o = (size_t)gw * CAP;
    #pragma unroll 1
    for (int it = 0; it < NN / 128; it++) {
        float4 v = ((const float4*)ar)[it * 32 + lane];
        float vv[4] = { v.x, v.y, v.z, v.w };
        #pragma unroll
        for (int j = 0; j < 4; j++) {
            bool nz = vv[j] > 0.f;
            unsigned m = __ballot_sync(0xffffffffu, nz);
            if (nz) {
                int pos = base + __popc(m & ((1u << lane) - 1u));
                if (pos < CAP) {
                    g_cols[o + pos] = bbase + it * 128 + lane * 4 + j;
                    g_vals[o + pos] = vv[j];
                }
            }
            base += __popc(m);
        }
    }
    if (lane == 0) g_cnt[gw] = min(base, CAP);
}

// ---------------- 2) fp32 -> bf16 hi/lo split converters ----------------
__global__ void conv_split(const float* __restrict__ x, __nv_bfloat16* __restrict__ hi,
                           __nv_bfloat16* __restrict__ lo, int n4) {
    int i = blockIdx.x * blockDim.x + threadIdx.x;
    if (i >= n4) return;
    float4 v = ((const float4*)x)[i];
    float f[4] = { v.x, v.y, v.z, v.w };
    ushort4 hh, ll;
    unsigned short* hp = &hh.x; unsigned short* lp = &ll.x;
    #pragma unroll
    for (int j = 0; j < 4; j++) {
        __nv_bfloat16 h = __float2bfloat16(f[j]);
        __nv_bfloat16 l = __float2bfloat16(f[j] - __bfloat162float(h));
        hp[j] = __bfloat16_as_ushort(h);
        lp[j] = __bfloat16_as_ushort(l);
    }
    ((ushort4*)hi)[i] = hh;
    ((ushort4*)lo)[i] = ll;
}

__global__ void conv_weights(const float* __restrict__ wfc, const float* __restrict__ wq,
                             const float* __restrict__ wk, const float* __restrict__ wv1,
                             const float* __restrict__ wv2) {
    int i = blockIdx.x * blockDim.x + threadIdx.x;
    if (i >= WTOT) return;
    float x;
    if      (i < WOFF_Q)  x = wfc[i];
    else if (i < WOFF_K)  x = wq [i - WOFF_Q];
    else if (i < WOFF_V1) x = wk [i - WOFF_K];
    else if (i < WOFF_V2) x = wv1[i - WOFF_V1];
    else                  x = wv2[i - WOFF_V2];
    __nv_bfloat16 h = __float2bfloat16(x);
    g_w_hi[i] = h;
    g_w_lo[i] = __float2bfloat16(x - __bfloat162float(h));
}

// ---------------- 3) split-bf16 mma.sync GEMM: C[m,n]=sum_k A[m,k]*W[n,k] ----------------
// A planes [M,K] bf16 row-major, W planes [N,K] bf16 row-major.
// CTA tile 128x64, 8 warps in 4(M)x2(N), warp tile 32x32.
// epi: 0 none, 1 prelu(alpha), 2 bias+prelu(alpha). outmode: 0 fp32 C, 1 bf16 planes.
__global__ __launch_bounds__(256, 2) void gemm_mma(
    const __nv_bfloat16* __restrict__ Ah, const __nv_bfloat16* __restrict__ Al,
    const __nv_bfloat16* __restrict__ Wh, const __nv_bfloat16* __restrict__ Wl,
    const float* __restrict__ bias, const float* __restrict__ alpha,
    float* __restrict__ C, __nv_bfloat16* __restrict__ Ch, __nv_bfloat16* __restrict__ Cl,
    int K, int epi, int outmode)
{
    __shared__ __align__(16) __nv_bfloat16 sAh[BM * LDS];
    __shared__ __align__(16) __nv_bfloat16 sAl[BM * LDS];
    __shared__ __align__(16) __nv_bfloat16 sBh[BN * LDS];
    __shared__ __align__(16) __nv_bfloat16 sBl[BN * LDS];

    const int t = threadIdx.x, lane = t & 31, wid = t >> 5;
    const int wm = wid & 3, wn = wid >> 2;
    const int m0 = blockIdx.y * BM, n0 = blockIdx.x * BN;

    float acc[2][4][4];
    #pragma unroll
    for (int i = 0; i < 2; i++)
        #pragma unroll
        for (int j = 0; j < 4; j++)
            #pragma unroll
            for (int l = 0; l < 4; l++) acc[i][j][l] = 0.f;

    // per-lane ldmatrix byte offsets (element offsets *2)
    uint32_t aAh_base = (uint32_t)__cvta_generic_to_shared(sAh);
    uint32_t aAl_base = (uint32_t)__cvta_generic_to_shared(sAl);
    uint32_t aBh_base = (uint32_t)__cvta_generic_to_shared(sBh);
    uint32_t aBl_base = (uint32_t)__cvta_generic_to_shared(sBl);
    uint32_t offA[2];
    #pragma unroll
    for (int mt = 0; mt < 2; mt++)
        offA[mt] = (uint32_t)(((wm * 32 + mt * 16 + (lane & 15)) * LDS + (lane >> 4) * 8) * 2);
    uint32_t offB[2];
    #pragma unroll
    for (int g = 0; g < 2; g++) {
        int nrow = wn * 32 + g * 16 + (lane & 7) + ((lane >> 4) & 1) * 8;
        int kof = ((lane >> 3) & 1) * 8;
        offB[g] = (uint32_t)((nrow * LDS + kof) * 2);
    }

    const int nchunk = K / KC;
    #pragma unroll 1
    for (int ko = 0; ko < nchunk; ko++) {
        const int k0 = ko * KC;
        #pragma unroll
        for (int i = 0; i < 2; i++) {
            int idx = t + i * 256;
            int row = idx >> 2, v = idx & 3;
            size_t go = (size_t)(m0 + row) * K + k0 + v * 8;
            *(uint4*)&sAh[row * LDS + v * 8] = *(const uint4*)&Ah[go];
            *(uint4*)&sAl[row * LDS + v * 8] = *(const uint4*)&Al[go];
        }
        {
            int row = t >> 2, v = t & 3;
            size_t go = (size_t)(n0 + row) * K + k0 + v * 8;
            *(uint4*)&sBh[row * LDS + v * 8] = *(const uint4*)&Wh[go];
            *(uint4*)&sBl[row * LDS + v * 8] = *(const uint4*)&Wl[go];
        }
        __syncthreads();

        #pragma unroll
        for (int ks = 0; ks < KC; ks += 16) {
            uint32_t ah[2][4], al[2][4], bh[2][4], bl[2][4];
            #pragma unroll
            for (int mt = 0; mt < 2; mt++) {
                ldsm_x4(ah[mt], aAh_base + offA[mt] + ks * 2);
                ldsm_x4(al[mt], aAl_base + offA[mt] + ks * 2);
            }
            #pragma unroll
            for (int g = 0; g < 2; g++) {
                ldsm_x4(bh[g], aBh_base + offB[g] + ks * 2);
                ldsm_x4(bl[g], aBl_base + offB[g] + ks * 2);
            }
            #pragma unroll
            for (int mt = 0; mt < 2; mt++)
                #pragma unroll
                for (int nb = 0; nb < 4; nb++) {
                    uint32_t bhj[2] = { bh[nb >> 1][(nb & 1) * 2], bh[nb >> 1][(nb & 1) * 2 + 1] };
                    uint32_t blj[2] = { bl[nb >> 1][(nb & 1) * 2], bl[nb >> 1][(nb & 1) * 2 + 1] };
                    mma_bf16(acc[mt][nb], ah[mt], bhj);
                    mma_bf16(acc[mt][nb], ah[mt], blj);
                    mma_bf16(acc[mt][nb], al[mt], bhj);
                }
        }
        __syncthreads();
    }

    // epilogue
    float av = (epi != 0) ? *alpha : 0.f;
    int mb = m0 + wm * 32 + (lane >> 2);
    int ncb = n0 + wn * 32 + (lane & 3) * 2;
    #pragma unroll
    for (int mt = 0; mt < 2; mt++)
        #pragma unroll
        for (int nb = 0; nb < 4; nb++)
            #pragma unroll
            for (int h = 0; h < 2; h++) {
                int m = mb + mt * 16 + h * 8;
                int n = ncb + nb * 8;
                float x0 = acc[mt][nb][h * 2 + 0];
                float x1 = acc[mt][nb][h * 2 + 1];
                if (epi == 2) { x0 += bias[n]; x1 += bias[n + 1]; }
                if (epi != 0) {
                    x0 = (x0 >= 0.f) ? x0 : av * x0;
                    x1 = (x1 >= 0.f) ? x1 : av * x1;
                }
                size_t co = (size_t)m * OUT_FT + n;
                if (outmode == 0) {
                    *(float2*)(C + co) = make_float2(x0, x1);
                } else {
                    __nv_bfloat16 h0 = __float2bfloat16(x0), h1 = __float2bfloat16(x1);
                    __nv_bfloat16 l0 = __float2bfloat16(x0 - __bfloat162float(h0));
                    __nv_bfloat16 l1 = __float2bfloat16(x1 - __bfloat162float(h1));
                    *(uint32_t*)(Ch + co) = (uint32_t)__bfloat16_as_ushort(h0) | ((uint32_t)__bfloat16_as_ushort(h1) << 16);
                    *(uint32_t*)(Cl + co) = (uint32_t)__bfloat16_as_ushort(l0) | ((uint32_t)__bfloat16_as_ushort(l1) << 16);
                }
            }
}

// ---------------- 4) SpMM + bf16 split epilogue ----------------
__global__ void spmm_kernel(const float* __restrict__ x, float* __restrict__ y,
                            __nv_bfloat16* __restrict__ yh, __nv_bfloat16* __restrict__ yl) {
    int row = blockIdx.x, t = threadIdx.x;
    __shared__ int   cs[CAP];
    __shared__ float vs[CAP];
    int nn = g_cnt[row];
    for (int j = t; j < nn; j += 256) {
        cs[j] = g_cols[(size_t)row * CAP + j];
        vs[j] = g_vals[(size_t)row * CAP + j];
    }
    __syncthreads();
    float acc = 0.f;
    #pragma unroll 4
    for (int j = 0; j < nn; j++)
        acc = fmaf(vs[j], x[(size_t)cs[j] * OUT_FT + t], acc);
    size_t idx = (size_t)row * OUT_FT + t;
    y[idx] = acc;
    __nv_bfloat16 h = __float2bfloat16(acc);
    yh[idx] = h;
    yl[idx] = __float2bfloat16(acc - __bfloat162float(h));
}

// ---------------- 5) normalize q,k in place; per-row ||q-k||^2 ----------------
__global__ void normalize_kernel(float* __restrict__ q, float* __restrict__ k,
                                 float* __restrict__ rowd) {
    __shared__ float red[8];
    int row = blockIdx.x, t = threadIdx.x;
    size_t idx = (size_t)row * OUT_FT + t;
    float qv = q[idx], kv = k[idx];
    float nq = sqrtf(blk_sum256(qv * qv, red));
    float nk = sqrtf(blk_sum256(kv * kv, red));
    float qn = qv / fmaxf(nq, EPSN);
    float kn = kv / fmaxf(nk, EPSN);
    q[idx] = qn; k[idx] = kn;
    float d = qn - kn;
    float ds = blk_sum256(d * d, red);
    if (t == 0) rowd[row] = ds;
}

__global__ void reduce_divloss(const float* __restrict__ rowd, float* __restrict__ dst) {
    __shared__ float sh[1024];
    int t = threadIdx.x;
    float s = 0.f;
    for (int i = t; i < ROWS; i += 1024) s += rowd[i];
    sh[t] = s; __syncthreads();
    #pragma unroll
    for (int o = 512; o; o >>= 1) { if (t < o) sh[t] += sh[t + o]; __syncthreads(); }
    if (t == 0) *dst = sh[0] / (float)ROWS;
}

// ---------------- 6) sparse masked softmax attention -> ctx (bf16 planes) ----------------
__global__ void attn_kernel(const float* __restrict__ q, const float* __restrict__ k,
                            const float* __restrict__ outm,
                            __nv_bfloat16* __restrict__ ch, __nv_bfloat16* __restrict__ cl) {
    int row = blockIdx.x, t = threadIdx.x, lane = t & 31, w = t >> 5;
    __shared__ float qs[OUT_FT];
    __shared__ int   cs[CAP];
    __shared__ float ss[CAP];
    __shared__ float red[8];
    int nn = g_cnt[row];
    qs[t] = q[(size_t)row * OUT_FT + t];
    for (int j = t; j < nn; j += 256) cs[j] = g_cols[(size_t)row * CAP + j];
    __syncthreads();
    for (int j = w; j < nn; j += 8) {
        const float* kr = k + (size_t)cs[j] * OUT_FT;
        float p = 0.f;
        #pragma unroll
        for (int i = 0; i < 8; i++) p = fmaf(qs[lane + 32 * i], kr[lane + 32 * i], p);
        #pragma unroll
        for (int o = 16; o; o >>= 1) p += __shfl_xor_sync(0xffffffffu, p, o);
        if (lane == 0) ss[j] = p;
    }
    __syncthreads();
    float mx = -3.0e38f;
    for (int j = t; j < nn; j += 256) mx = fmaxf(mx, ss[j]);
    mx = blk_max256(mx, red);
    float sm = 0.f;
    for (int j = t; j < nn; j += 256) { float e = expf(ss[j] - mx); ss[j] = e; sm += e; }
    sm = blk_sum256(sm, red);
    float inv = 1.f / sm;
    float acc = 0.f;
    #pragma unroll 4
    for (int j = 0; j < nn; j++)
        acc = fmaf(ss[j] * inv, outm[(size_t)cs[j] * OUT_FT + t], acc);
    size_t idx = (size_t)row * OUT_FT + t;
    __nv_bfloat16 h = __float2bfloat16(acc);
    ch[idx] = h;
    cl[idx] = __float2bfloat16(acc - __bfloat162float(h));
}

// ---------------- host ----------------
extern "C" void kernel_launch(void* const* d_in, const int* in_sizes, int n_in,
                              void* d_out, int out_size) {
    const float* seq   = (const float*)d_in[0];
    const float* adj   = (const float*)d_in[1];
    const float* W_fc  = (const float*)d_in[2];
    const float* W_q   = (const float*)d_in[3];
    const float* W_k   = (const float*)d_in[4];
    const float* W_v1  = (const float*)d_in[5];
    const float* W_v2  = (const float*)d_in[6];
    const float* a_v   = (const float*)d_in[7];
    const float* a_act = (const float*)d_in[8];
    const float* bias  = (const float*)d_in[9];
    float* out = (float*)d_out;

    float *p_seqfts, *p_out, *p_q, *p_k, *p_rowd;
    __nv_bfloat16 *p_seq_hi, *p_seq_lo, *p_out_hi, *p_out_lo, *p_ctx_hi, *p_ctx_lo, *p_h_hi, *p_h_lo, *p_w_hi, *p_w_lo;
    cudaGetSymbolAddress((void**)&p_seqfts, g_seqfts);
    cudaGetSymbolAddress((void**)&p_out,    g_out);
    cudaGetSymbolAddress((void**)&p_q,      g_q);
    cudaGetSymbolAddress((void**)&p_k,      g_k);
    cudaGetSymbolAddress((void**)&p_rowd,   g_rowd);
    cudaGetSymbolAddress((void**)&p_seq_hi, g_seq_hi);
    cudaGetSymbolAddress((void**)&p_seq_lo, g_seq_lo);
    cudaGetSymbolAddress((void**)&p_out_hi, g_out_hi);
    cudaGetSymbolAddress((void**)&p_out_lo, g_out_lo);
    cudaGetSymbolAddress((void**)&p_ctx_hi, g_ctx_hi);
    cudaGetSymbolAddress((void**)&p_ctx_lo, g_ctx_lo);
    cudaGetSymbolAddress((void**)&p_h_hi,   g_h_hi);
    cudaGetSymbolAddress((void**)&p_h_lo,   g_h_lo);
    cudaGetSymbolAddress((void**)&p_w_hi,   g_w_hi);
    cudaGetSymbolAddress((void**)&p_w_lo,   g_w_lo);

    dim3 gg(OUT_FT / BN, ROWS / BM);   // (4, 64)

    build_sparse<<<ROWS / 8, 256>>>(adj);
    conv_split<<<(ROWS * IN_FT / 4 + 255) / 256, 256>>>(seq, p_seq_hi, p_seq_lo, ROWS * IN_FT / 4);
    conv_weights<<<(WTOT + 255) / 256, 256>>>(W_fc, W_q, W_k, W_v1, W_v2);

    gemm_mma<<<gg, 256>>>(p_seq_hi, p_seq_lo, p_w_hi + WOFF_FC, p_w_lo + WOFF_FC,
                          nullptr, nullptr, p_seqfts, nullptr, nullptr, IN_FT, 0, 0);
    spmm_kernel<<<ROWS, 256>>>(p_seqfts, p_out, p_out_hi, p_out_lo);
    gemm_mma<<<gg, 256>>>(p_out_hi, p_out_lo, p_w_hi + WOFF_Q, p_w_lo + WOFF_Q,
                          nullptr, nullptr, p_q, nullptr, nullptr, OUT_FT, 0, 0);
    gemm_mma<<<gg, 256>>>(p_out_hi, p_out_lo, p_w_hi + WOFF_K, p_w_lo + WOFF_K,
                          nullptr, nullptr, p_k, nullptr, nullptr, OUT_FT, 0, 0);
    normalize_kernel<<<ROWS, 256>>>(p_q, p_k, p_rowd);
    if (out_size >= ROWS * OUT_FT + 1)
        reduce_divloss<<<1, 1024>>>(p_rowd, out + (size_t)ROWS * OUT_FT);
    attn_kernel<<<ROWS, 256>>>(p_q, p_k, p_out, p_ctx_hi, p_ctx_lo);
    gemm_mma<<<gg, 256>>>(p_ctx_hi, p_ctx_lo, p_w_hi + WOFF_V1, p_w_lo + WOFF_V1,
                          nullptr, a_v, nullptr, p_h_hi, p_h_lo, OUT_FT, 1, 1);
    gemm_mma<<<gg, 256>>>(p_h_hi, p_h_lo, p_w_hi + WOFF_V2, p_w_lo + WOFF_V2,
                          bias, a_act, out, nullptr, nullptr, OUT_FT, 2, 0);
}